// round 14
// baseline (speedup 1.0000x reference)
#include <cuda_runtime.h>
#include <cuda_fp16.h>
#include <cstddef>
#include <cstdint>

#define NPF 60000
#define NGW 300000
#define NSW 60000
#define EMAX 1000000

// ---------------- scratch layout (4-byte units, ALL multiples of 4) ----------------
static const size_t OFF_H1     = 0;           // h1 fp16 (13.44M halves)
static const size_t OFF_CNT    = 26880000;
static const size_t OFF_FILL   = 28043264;
static const size_t OFF_INCL   = 29206528;
static const size_t OFF_BSUMS  = 30369792;    // 7*512
static const size_t OFF_ROWPTR = 30373376;    // padded to 1,140,008
static const size_t OFF_COLIDX = 31513384;    // 7,000,000
static const size_t OFF_WCAT   = 38513384;    // ~62k floats
static const size_t OFF_X16    = 38575216;    // x as fp16: 13.44M halves = 6.72M floats

__device__ float g_scratch[45300000];   // ~181 MB

// types: 0 pf_gw, 1 sw_gw, 2 gw_gw, 3 gw_pf, 4 sw_pf, 5 pf_sw, 6 gw_sw
struct ScanCfg { int ps[7]; int nblk[7]; int n[7]; int rpo[7]; };
struct Ptrs7i { const int* p[7]; };
struct Ptrs7o { int* p[7]; };

// ---------------- x -> fp16 conversion ----------------
struct CvtCfg { const float* src[3]; __half* dst[3]; int n4[3]; };  // n4 = float4 count
__global__ void convert_x16(CvtCfg cc) {
    int t = blockIdx.y;
    int i = blockIdx.x * blockDim.x + threadIdx.x;
    if (i >= cc.n4[t]) return;
    float4 v = reinterpret_cast<const float4*>(cc.src[t])[i];
    __half2 h01 = __floats2half2_rn(v.x, v.y);
    __half2 h23 = __floats2half2_rn(v.z, v.w);
    uint2 o;
    o.x = *reinterpret_cast<uint32_t*>(&h01);
    o.y = *reinterpret_cast<uint32_t*>(&h23);
    reinterpret_cast<uint2*>(cc.dst[t])[i] = o;
}

// ---------------- CSR build (batched) ----------------
__global__ void count_all(Ptrs7i ei, Ptrs7o cnt, int E) {
    int t = blockIdx.y;
    int i = blockIdx.x * blockDim.x + threadIdx.x;
    if (i < E) atomicAdd(&cnt.p[t][ei.p[t][E + i]], 1);
}

// warp-shuffle block scan (2 barriers)
__global__ void scan_partial(const int* __restrict__ cnt, int* __restrict__ incl,
                             int* __restrict__ bsums, ScanCfg sc) {
    int t = blockIdx.y;
    if ((int)blockIdx.x >= sc.nblk[t]) return;
    __shared__ int wsum[32];
    int tid = threadIdx.x;
    int lane = tid & 31, w = tid >> 5;
    int base = sc.ps[t] + blockIdx.x * 1024;
    int x = cnt[base + tid];
#pragma unroll
    for (int off = 1; off < 32; off <<= 1) {
        int y = __shfl_up_sync(0xffffffffu, x, off);
        if (lane >= off) x += y;
    }
    if (lane == 31) wsum[w] = x;
    __syncthreads();
    if (w == 0) {
        int s = wsum[lane];
#pragma unroll
        for (int off = 1; off < 32; off <<= 1) {
            int y = __shfl_up_sync(0xffffffffu, s, off);
            if (lane >= off) s += y;
        }
        wsum[lane] = s;
    }
    __syncthreads();
    int add = (w > 0) ? wsum[w - 1] : 0;
    int inc = x + add;
    incl[base + tid] = inc;
    if (tid == 1023) bsums[t * 512 + blockIdx.x] = inc;
}

__global__ void scan_bsums(int* __restrict__ bs, ScanCfg sc) {
    int t = blockIdx.y;
    int nb = sc.nblk[t];
    __shared__ int s[512];
    int tid = threadIdx.x;
    int v = (tid < nb) ? bs[t * 512 + tid] : 0;
    s[tid] = v; __syncthreads();
#pragma unroll
    for (int off = 1; off < 512; off <<= 1) {
        int t2 = (tid >= off) ? s[tid - off] : 0;
        __syncthreads();
        s[tid] += t2;
        __syncthreads();
    }
    if (tid < nb) bs[t * 512 + tid] = s[tid] - v;   // exclusive
}

__global__ void scan_final(const int* __restrict__ incl, const int* __restrict__ bs,
                           int* __restrict__ rowptr, ScanCfg sc) {
    int t = blockIdx.y;
    int i = blockIdx.x * blockDim.x + threadIdx.x;
    int n = sc.n[t];
    if (i < n) rowptr[sc.rpo[t] + i + 1] = incl[sc.ps[t] + i] + bs[t * 512 + (i >> 10)];
    if (i == 0) rowptr[sc.rpo[t]] = 0;
}

__global__ void scatter_all(Ptrs7i ei, Ptrs7i rp, Ptrs7o fill, Ptrs7o col, int E) {
    int t = blockIdx.y;
    int i = blockIdx.x * blockDim.x + threadIdx.x;
    if (i < E) {
        int s = ei.p[t][i];
        int d = ei.p[t][E + i];
        int pos = rp.p[t][d] + atomicAdd(&fill.p[t][d], 1);
        col.p[t][pos] = s;
    }
}

// ---------------- combined weights (batched, emit fp16) ----------------
struct WCfg {
    const float* Wl; const float* Wr; const float* b;
    __half* w; float* bc;
    int Din, nm, selfid, m0, m1, m2;
};
struct WAll { WCfg c[6]; };

__global__ void build_wcat_all(WAll wa) {
    WCfg cf = wa.c[blockIdx.y];
    int K = (cf.nm + 1) * cf.Din;
    int idx = blockIdx.x * blockDim.x + threadIdx.x;
    if (idx >= 64 * K) return;
    int d = idx / K, c = idx % K;
    int seg = c / cf.Din, k = c % cf.Din;
    int ms[3] = {cf.m0, cf.m1, cf.m2};
    int stride = 64 * cf.Din;
    float v;
    if (seg < cf.nm) {
        v = cf.Wl[ms[seg] * stride + d * cf.Din + k];
    } else {
        v = cf.Wl[cf.selfid * stride + d * cf.Din + k] + cf.Wr[cf.selfid * stride + d * cf.Din + k];
        for (int i = 0; i < cf.nm; i++) v += cf.Wr[ms[i] * stride + d * cf.Din + k];
    }
    cf.w[d * K + c] = __float2half_rn(v);
    if (c == 0) {
        float bb = cf.b[cf.selfid * 64 + d];
        for (int i = 0; i < cf.nm; i++) bb += cf.b[ms[i] * 64 + d];
        cf.bc[d] = bb;
    }
}

// ---------------- fused gather + fp16 tensor GEMM ----------------
__device__ __forceinline__ void mma_f16(float& d0, float& d1, float& d2, float& d3,
                                        uint32_t a0, uint32_t a1, uint32_t a2, uint32_t a3,
                                        uint32_t b0, uint32_t b1) {
    asm volatile("mma.sync.aligned.m16n8k16.row.col.f32.f16.f16.f32 "
                 "{%0,%1,%2,%3}, {%4,%5,%6,%7}, {%8,%9}, {%0,%1,%2,%3};"
                 : "+f"(d0), "+f"(d1), "+f"(d2), "+f"(d3)
                 : "r"(a0), "r"(a1), "r"(a2), "r"(a3), "r"(b0), "r"(b1));
}

__device__ __forceinline__ void acc_h4(float4& a, uint2 rw) {
    __half2 h0 = *reinterpret_cast<__half2*>(&rw.x);
    __half2 h1 = *reinterpret_cast<__half2*>(&rw.y);
    float2 f0 = __half22float2(h0);
    float2 f1 = __half22float2(h1);
    a.x += f0.x; a.y += f0.y; a.z += f1.x; a.w += f1.y;
}

struct TypeParams {
    const int* rp[3];
    const int* ci[3];
    const __half* src[3];
    const __half* xself;
    const __half* wcat;
    const float* bcat;
    float* out;
    int N;
    int nseg;
    int K;
    int mode;   // 0: fp16 [N,64]; 1: prelu scalar; 2: fp32 [N,64]
    int blk0;
};
struct LayerParams {
    TypeParams t[3];
    const float* linW; const float* linb; const float* pa;
};

template <int DIN>
__global__ void __launch_bounds__(512, 3) fused_multi(LayerParams lp) {
    constexpr int S2 = DIN + 8;           // smem row stride in halves
    constexpr int G = DIN / 4;            // 4 halves per lane
    constexpr int NPI = 512 / G;
    constexpr int NIT = 128 / NPI;
    constexpr int C8 = DIN / 8;           // uint4 chunks per weight row

    __shared__ __half sA[128 * S2];
    __shared__ __half sB[64 * S2];
    __shared__ float sred[512];

    int bx = blockIdx.x;
    int ty = (bx >= lp.t[2].blk0) ? 2 : (bx >= lp.t[1].blk0) ? 1 : 0;
    const TypeParams& tp = lp.t[ty];
    int nbase = (bx - tp.blk0) * 128;
    int N = tp.N;
    int nseg = tp.nseg;
    int K = tp.K;

    int tid = threadIdx.x;
    int warp = tid >> 5, lane = tid & 31;
    int wm = warp >> 2, wn = warp & 3;
    int r = lane >> 2, c = lane & 3;

    float acc[2][2][4];
#pragma unroll
    for (int mi = 0; mi < 2; mi++)
#pragma unroll
        for (int ni = 0; ni < 2; ni++) {
            int col = wn * 16 + ni * 8 + 2 * c;
            acc[mi][ni][0] = acc[mi][ni][2] = tp.bcat[col];
            acc[mi][ni][1] = acc[mi][ni][3] = tp.bcat[col + 1];
        }

    int g = tid & (G - 1);
    int nl0 = tid / G;

    for (int seg = 0; seg <= nseg; seg++) {
        bool isself = (seg == nseg);
        const int* rp = tp.rp[isself ? 0 : seg];
        const int* ci = tp.ci[isself ? 0 : seg];
        const __half* src = tp.src[isself ? 0 : seg];

        // ---- stage fp16 weight slice [64][DIN] ----
        if (tid < 64 * C8) {
            int row = tid / C8, cc = tid % C8;
            uint4 w = *reinterpret_cast<const uint4*>(tp.wcat + (size_t)row * K + seg * DIN + cc * 8);
            *reinterpret_cast<uint4*>(&sB[(size_t)row * S2 + cc * 8]) = w;
        }

        // ---- gather / copy A slice [128][DIN] into fp16 smem ----
#pragma unroll
        for (int it = 0; it < NIT; it++) {
            int nl = it * NPI + nl0;
            int node = nbase + nl;
            bool valid = node < N;
            __half* ar = &sA[(size_t)nl * S2 + g * 4];
            uint2 stv;
            if (!isself) {
                int beg = 0, end = 0;
                if (valid) { beg = rp[node]; end = rp[node + 1]; }
                float4 a4 = make_float4(0.f, 0.f, 0.f, 0.f);
                const __half* sp = src + g * 4;
                int e = beg;
                for (; e + 4 <= end; e += 4) {
                    int i0 = ci[e], i1 = ci[e + 1], i2 = ci[e + 2], i3 = ci[e + 3];
                    uint2 v0 = *reinterpret_cast<const uint2*>(sp + (size_t)i0 * DIN);
                    uint2 v1 = *reinterpret_cast<const uint2*>(sp + (size_t)i1 * DIN);
                    uint2 v2 = *reinterpret_cast<const uint2*>(sp + (size_t)i2 * DIN);
                    uint2 v3 = *reinterpret_cast<const uint2*>(sp + (size_t)i3 * DIN);
                    acc_h4(a4, v0); acc_h4(a4, v1); acc_h4(a4, v2); acc_h4(a4, v3);
                }
                for (; e < end; e++) {
                    uint2 v0 = *reinterpret_cast<const uint2*>(sp + (size_t)ci[e] * DIN);
                    acc_h4(a4, v0);
                }
                float inv = (end > beg) ? 1.0f / (float)(end - beg) : 0.0f;
                __half2 h01 = __floats2half2_rn(a4.x * inv, a4.y * inv);
                __half2 h23 = __floats2half2_rn(a4.z * inv, a4.w * inv);
                stv.x = *reinterpret_cast<uint32_t*>(&h01);
                stv.y = *reinterpret_cast<uint32_t*>(&h23);
            } else {
                stv = make_uint2(0u, 0u);
                if (valid) stv = *reinterpret_cast<const uint2*>(tp.xself + (size_t)node * DIN + g * 4);
            }
            *reinterpret_cast<uint2*>(ar) = stv;
        }
        __syncthreads();

        // ---- f16 mma over this K-chunk (k16 steps) ----
#pragma unroll
        for (int k0 = 0; k0 < DIN; k0 += 16) {
            uint32_t bf0[2], bf1[2];
#pragma unroll
            for (int ni = 0; ni < 2; ni++) {
                const __half* pb = &sB[(size_t)(wn * 16 + ni * 8 + r) * S2 + k0 + 2 * c];
                bf0[ni] = *reinterpret_cast<const uint32_t*>(pb);
                bf1[ni] = *reinterpret_cast<const uint32_t*>(pb + 8);
            }
#pragma unroll
            for (int mi = 0; mi < 2; mi++) {
                const __half* pa = &sA[(size_t)(wm * 32 + mi * 16 + r) * S2 + k0 + 2 * c];
                uint32_t a0 = *reinterpret_cast<const uint32_t*>(pa);
                uint32_t a1 = *reinterpret_cast<const uint32_t*>(pa + 8 * S2);
                uint32_t a2 = *reinterpret_cast<const uint32_t*>(pa + 8);
                uint32_t a3 = *reinterpret_cast<const uint32_t*>(pa + 8 * S2 + 8);
#pragma unroll
                for (int ni = 0; ni < 2; ni++)
                    mma_f16(acc[mi][ni][0], acc[mi][ni][1], acc[mi][ni][2], acc[mi][ni][3],
                            a0, a1, a2, a3, bf0[ni], bf1[ni]);
            }
        }
        __syncthreads();
    }

    // ---- epilogue ----
    if (tp.mode == 0) {
        __half* o16 = reinterpret_cast<__half*>(tp.out);
#pragma unroll
        for (int mi = 0; mi < 2; mi++) {
            int m0 = nbase + wm * 32 + mi * 16 + r;
#pragma unroll
            for (int ni = 0; ni < 2; ni++) {
                int col = wn * 16 + ni * 8 + 2 * c;
                if (m0 < N) {
                    __half2 v = __floats2half2_rn(fmaxf(acc[mi][ni][0], 0.f), fmaxf(acc[mi][ni][1], 0.f));
                    *reinterpret_cast<uint32_t*>(o16 + (size_t)m0 * 64 + col) = *reinterpret_cast<uint32_t*>(&v);
                }
                if (m0 + 8 < N) {
                    __half2 v = __floats2half2_rn(fmaxf(acc[mi][ni][2], 0.f), fmaxf(acc[mi][ni][3], 0.f));
                    *reinterpret_cast<uint32_t*>(o16 + (size_t)(m0 + 8) * 64 + col) = *reinterpret_cast<uint32_t*>(&v);
                }
            }
        }
    } else if (tp.mode == 2) {
        float* outp = tp.out;
#pragma unroll
        for (int mi = 0; mi < 2; mi++) {
            int m0 = nbase + wm * 32 + mi * 16 + r;
#pragma unroll
            for (int ni = 0; ni < 2; ni++) {
                int col = wn * 16 + ni * 8 + 2 * c;
                if (m0 < N) {
                    float2 v = make_float2(fmaxf(acc[mi][ni][0], 0.f), fmaxf(acc[mi][ni][1], 0.f));
                    *reinterpret_cast<float2*>(outp + (size_t)m0 * 64 + col) = v;
                }
                if (m0 + 8 < N) {
                    float2 v = make_float2(fmaxf(acc[mi][ni][2], 0.f), fmaxf(acc[mi][ni][3], 0.f));
                    *reinterpret_cast<float2*>(outp + (size_t)(m0 + 8) * 64 + col) = v;
                }
            }
        }
    } else {
        float lb = lp.linb[0];
        float ap = lp.pa[0];
        float pl[2] = {0.f, 0.f}, ph[2] = {0.f, 0.f};
#pragma unroll
        for (int mi = 0; mi < 2; mi++) {
#pragma unroll
            for (int ni = 0; ni < 2; ni++) {
                int col = wn * 16 + ni * 8 + 2 * c;
                float w0 = lp.linW[col], w1 = lp.linW[col + 1];
                pl[mi] += fmaxf(acc[mi][ni][0], 0.f) * w0 + fmaxf(acc[mi][ni][1], 0.f) * w1;
                ph[mi] += fmaxf(acc[mi][ni][2], 0.f) * w0 + fmaxf(acc[mi][ni][3], 0.f) * w1;
            }
            pl[mi] += __shfl_xor_sync(0xffffffffu, pl[mi], 1);
            pl[mi] += __shfl_xor_sync(0xffffffffu, pl[mi], 2);
            ph[mi] += __shfl_xor_sync(0xffffffffu, ph[mi], 1);
            ph[mi] += __shfl_xor_sync(0xffffffffu, ph[mi], 2);
        }
        if (c == 0) {
#pragma unroll
            for (int mi = 0; mi < 2; mi++) {
                sred[wn * 128 + wm * 32 + mi * 16 + r] = pl[mi];
                sred[wn * 128 + wm * 32 + mi * 16 + r + 8] = ph[mi];
            }
        }
        __syncthreads();
        if (tid < 128) {
            float v = sred[tid] + sred[128 + tid] + sred[256 + tid] + sred[384 + tid] + lb;
            int n = nbase + tid;
            if (n < N) tp.out[n] = (v >= 0.f) ? v : ap * v;
        }
    }
}

// ---------------- launch ----------------
extern "C" void kernel_launch(void* const* d_in, const int* in_sizes, int n_in,
                              void* d_out, int out_size) {
    const float* x_pf = (const float*)d_in[0];
    const float* x_gw = (const float*)d_in[1];
    const float* x_sw = (const float*)d_in[2];
    const float* W1l  = (const float*)d_in[3];
    const float* b1l  = (const float*)d_in[4];
    const float* W1r  = (const float*)d_in[5];
    const float* W2l  = (const float*)d_in[6];
    const float* b2l  = (const float*)d_in[7];
    const float* W2r  = (const float*)d_in[8];
    const float* linW = (const float*)d_in[9];
    const float* linb = (const float*)d_in[10];
    const float* pa   = (const float*)d_in[11];
    const int* eis[7] = {
        (const int*)d_in[12],  // pf_gw
        (const int*)d_in[16],  // sw_gw
        (const int*)d_in[18],  // gw_gw
        (const int*)d_in[13],  // gw_pf
        (const int*)d_in[15],  // sw_pf
        (const int*)d_in[14],  // pf_sw
        (const int*)d_in[17],  // gw_sw
    };
    float* out = (float*)d_out;
    int E = in_sizes[12] / 2;

    float* scr;
    cudaGetSymbolAddress((void**)&scr, g_scratch);

    __half* h1_pf = reinterpret_cast<__half*>(scr + OFF_H1);
    __half* h1_gw = h1_pf + (size_t)NPF * 64;
    __half* h1_sw = h1_gw + (size_t)NGW * 64;

    __half* x16_pf = reinterpret_cast<__half*>(scr + OFF_X16);
    __half* x16_gw = x16_pf + (size_t)NPF * 32;
    __half* x16_sw = x16_gw + (size_t)NGW * 32;

    int* cnt_base    = (int*)(scr + OFF_CNT);
    int* fill_base   = (int*)(scr + OFF_FILL);
    int* incl        = (int*)(scr + OFF_INCL);
    int* bsums       = (int*)(scr + OFF_BSUMS);
    int* rowptr_base = (int*)(scr + OFF_ROWPTR);
    int* colidx_base = (int*)(scr + OFF_COLIDX);

    const int ns[7] = {NGW, NGW, NGW, NPF, NPF, NSW, NSW};
    ScanCfg sc;
    int cnt_pad_total = 0;
    {
        int po = 0, ro = 0;
        for (int t = 0; t < 7; t++) {
            sc.ps[t] = po;
            sc.n[t] = ns[t];
            sc.nblk[t] = (ns[t] + 1023) / 1024;
            sc.rpo[t] = ro;
            po += sc.nblk[t] * 1024;
            ro += ns[t] + 1;
        }
        cnt_pad_total = po;
    }

    Ptrs7i pei, prp;
    Ptrs7o pcnt, pfill, pcol;
    int* rps[7]; int* cols[7];
    for (int t = 0; t < 7; t++) {
        pei.p[t]  = eis[t];
        pcnt.p[t] = cnt_base + sc.ps[t];
        pfill.p[t] = fill_base + sc.ps[t];
        rps[t] = rowptr_base + sc.rpo[t];
        prp.p[t] = rps[t];
        cols[t] = colidx_base + (size_t)t * EMAX;
        pcol.p[t] = cols[t];
    }

    float* wbase  = scr + OFF_WCAT;
    __half* wL1_gw = (__half*)(wbase);
    __half* wL1_pf = (__half*)(wbase + 8192);
    __half* wL1_sw = (__half*)(wbase + 14336);
    __half* wL2_gw = (__half*)(wbase + 20480);
    __half* wL2_pf = (__half*)(wbase + 36864);
    __half* wL2_sw = (__half*)(wbase + 49152);
    float* bL1_gw = wbase + 61440;
    float* bL1_pf = bL1_gw + 64;
    float* bL1_sw = bL1_pf + 64;
    float* bL2_gw = bL1_sw + 64;
    float* bL2_pf = bL2_gw + 64;
    float* bL2_sw = bL2_pf + 64;

    // ---- x -> fp16 ----
    {
        CvtCfg cc;
        cc.src[0] = x_pf; cc.dst[0] = x16_pf; cc.n4[0] = NPF * 8;
        cc.src[1] = x_gw; cc.dst[1] = x16_gw; cc.n4[1] = NGW * 8;
        cc.src[2] = x_sw; cc.dst[2] = x16_sw; cc.n4[2] = NSW * 8;
        dim3 g((NGW * 8 + 255) / 256, 3);
        convert_x16<<<g, 256>>>(cc);
    }

    // ---- CSR build ----
    cudaMemsetAsync(cnt_base, 0, (size_t)cnt_pad_total * sizeof(int), 0);
    cudaMemsetAsync(fill_base, 0, (size_t)cnt_pad_total * sizeof(int), 0);
    {
        dim3 g((E + 255) / 256, 7);
        count_all<<<g, 256>>>(pei, pcnt, E);
    }
    {
        dim3 g(300, 7);
        scan_partial<<<g, 1024>>>(cnt_base, incl, bsums, sc);
        dim3 g2(1, 7);
        scan_bsums<<<g2, 512>>>(bsums, sc);
        dim3 g3((NGW + 255) / 256, 7);
        scan_final<<<g3, 256>>>(incl, bsums, rowptr_base, sc);
    }
    {
        dim3 g((E + 255) / 256, 7);
        scatter_all<<<g, 256>>>(pei, prp, pfill, pcol, E);
    }

    // ---- weights (fp16) ----
    {
        WAll wa;
        wa.c[0] = {W1l, W1r, b1l, wL1_gw, bL1_gw, 32, 3, 7, 0, 4, 6};
        wa.c[1] = {W1l, W1r, b1l, wL1_pf, bL1_pf, 32, 2, 9, 1, 3, -1};
        wa.c[2] = {W1l, W1r, b1l, wL1_sw, bL1_sw, 32, 2, 8, 2, 5, -1};
        wa.c[3] = {W2l, W2r, b2l, wL2_gw, bL2_gw, 64, 3, 7, 0, 4, 6};
        wa.c[4] = {W2l, W2r, b2l, wL2_pf, bL2_pf, 64, 2, 9, 1, 3, -1};
        wa.c[5] = {W2l, W2r, b2l, wL2_sw, bL2_sw, 64, 2, 8, 2, 5, -1};
        dim3 g(64, 6);
        build_wcat_all<<<g, 256>>>(wa);
    }

    const int BGW = (NGW + 127) / 128;   // 2344
    const int BPF = (NPF + 127) / 128;   // 469
    const int BSW = (NSW + 127) / 128;   // 469
    const int BTOT = BGW + BPF + BSW;    // 3282

    // ---- layer 1 (Din=32, fp16 x sources -> fp16 h1) ----
    {
        LayerParams lp;
        lp.linW = linW; lp.linb = linb; lp.pa = pa;
        lp.t[0] = {{rps[0], rps[1], rps[2]}, {cols[0], cols[1], cols[2]},
                   {x16_pf, x16_sw, x16_gw}, x16_gw, wL1_gw, bL1_gw, (float*)h1_gw,
                   NGW, 3, 128, 0, 0};
        lp.t[1] = {{rps[3], rps[4], rps[4]}, {cols[3], cols[4], cols[4]},
                   {x16_gw, x16_sw, x16_sw}, x16_pf, wL1_pf, bL1_pf, (float*)h1_pf,
                   NPF, 2, 96, 0, BGW};
        lp.t[2] = {{rps[5], rps[6], rps[6]}, {cols[5], cols[6], cols[6]},
                   {x16_pf, x16_gw, x16_gw}, x16_sw, wL1_sw, bL1_sw, (float*)h1_sw,
                   NSW, 2, 96, 0, BGW + BPF};
        fused_multi<32><<<BTOT, 512>>>(lp);
    }

    // ---- layer 2 (Din=64, fp16 h1 sources) ----
    // out layout: out_gw [NGW], out_sw [NSW], h_pf [NPF*64]
    {
        LayerParams lp;
        lp.linW = linW; lp.linb = linb; lp.pa = pa;
        lp.t[0] = {{rps[0], rps[1], rps[2]}, {cols[0], cols[1], cols[2]},
                   {h1_pf, h1_sw, h1_gw}, h1_gw, wL2_gw, bL2_gw, out,
                   NGW, 3, 256, 1, 0};
        lp.t[1] = {{rps[3], rps[4], rps[4]}, {cols[3], cols[4], cols[4]},
                   {h1_gw, h1_sw, h1_sw}, h1_pf, wL2_pf, bL2_pf, out + NGW + NSW,
                   NPF, 2, 192, 2, BGW};
        lp.t[2] = {{rps[5], rps[6], rps[6]}, {cols[5], cols[6], cols[6]},
                   {h1_pf, h1_gw, h1_gw}, h1_sw, wL2_sw, bL2_sw, out + NGW,
                   NSW, 2, 192, 1, BGW + BPF};
        fused_multi<64><<<BTOT, 512>>>(lp);
    }
}

// round 15
// speedup vs baseline: 1.4629x; 1.4629x over previous
#include <cuda_runtime.h>
#include <cuda_fp16.h>
#include <cstddef>
#include <cstdint>

#define NPF 60000
#define NGW 300000
#define NSW 60000
#define EMAX 1000000

// ---------------- scratch layout (4-byte units, ALL multiples of 4) ----------------
static const size_t OFF_H1     = 0;           // h1 as fp16 halves
static const size_t OFF_CNT    = 26880000;
static const size_t OFF_FILL   = 28043264;
static const size_t OFF_INCL   = 29206528;
static const size_t OFF_BSUMS  = 30369792;    // 7*512
static const size_t OFF_ROWPTR = 30373376;    // padded to 1,140,008
static const size_t OFF_COLIDX = 31513384;    // 7,000,000
static const size_t OFF_WCAT   = 38513384;    // float-sized slots, used as halves

__device__ float g_scratch[38600000];   // ~155 MB

// types: 0 pf_gw, 1 sw_gw, 2 gw_gw, 3 gw_pf, 4 sw_pf, 5 pf_sw, 6 gw_sw
struct ScanCfg { int ps[7]; int nblk[7]; int n[7]; int rpo[7]; };
struct Ptrs7i { const int* p[7]; };
struct Ptrs7o { int* p[7]; };

// ---------------- CSR build (batched) ----------------
__global__ void count_all(Ptrs7i ei, Ptrs7o cnt, int E) {
    int t = blockIdx.y;
    int i = blockIdx.x * blockDim.x + threadIdx.x;
    if (i < E) atomicAdd(&cnt.p[t][ei.p[t][E + i]], 1);
}

// warp-shuffle block scan (2 barriers)
__global__ void scan_partial(const int* __restrict__ cnt, int* __restrict__ incl,
                             int* __restrict__ bsums, ScanCfg sc) {
    int t = blockIdx.y;
    if ((int)blockIdx.x >= sc.nblk[t]) return;
    __shared__ int wsum[32];
    int tid = threadIdx.x;
    int lane = tid & 31, w = tid >> 5;
    int base = sc.ps[t] + blockIdx.x * 1024;
    int x = cnt[base + tid];
#pragma unroll
    for (int off = 1; off < 32; off <<= 1) {
        int y = __shfl_up_sync(0xffffffffu, x, off);
        if (lane >= off) x += y;
    }
    if (lane == 31) wsum[w] = x;
    __syncthreads();
    if (w == 0) {
        int s = wsum[lane];
#pragma unroll
        for (int off = 1; off < 32; off <<= 1) {
            int y = __shfl_up_sync(0xffffffffu, s, off);
            if (lane >= off) s += y;
        }
        wsum[lane] = s;
    }
    __syncthreads();
    int add = (w > 0) ? wsum[w - 1] : 0;
    int inc = x + add;
    incl[base + tid] = inc;
    if (tid == 1023) bsums[t * 512 + blockIdx.x] = inc;
}

__global__ void scan_bsums(int* __restrict__ bs, ScanCfg sc) {
    int t = blockIdx.y;
    int nb = sc.nblk[t];
    __shared__ int s[512];
    int tid = threadIdx.x;
    int v = (tid < nb) ? bs[t * 512 + tid] : 0;
    s[tid] = v; __syncthreads();
#pragma unroll
    for (int off = 1; off < 512; off <<= 1) {
        int t2 = (tid >= off) ? s[tid - off] : 0;
        __syncthreads();
        s[tid] += t2;
        __syncthreads();
    }
    if (tid < nb) bs[t * 512 + tid] = s[tid] - v;   // exclusive
}

__global__ void scan_final(const int* __restrict__ incl, const int* __restrict__ bs,
                           int* __restrict__ rowptr, ScanCfg sc) {
    int t = blockIdx.y;
    int i = blockIdx.x * blockDim.x + threadIdx.x;
    int n = sc.n[t];
    if (i < n) rowptr[sc.rpo[t] + i + 1] = incl[sc.ps[t] + i] + bs[t * 512 + (i >> 10)];
    if (i == 0) rowptr[sc.rpo[t]] = 0;
}

__global__ void scatter_all(Ptrs7i ei, Ptrs7i rp, Ptrs7o fill, Ptrs7o col, int E) {
    int t = blockIdx.y;
    int i = blockIdx.x * blockDim.x + threadIdx.x;
    if (i < E) {
        int s = ei.p[t][i];
        int d = ei.p[t][E + i];
        int pos = rp.p[t][d] + atomicAdd(&fill.p[t][d], 1);
        col.p[t][pos] = s;
    }
}

// ---------------- combined weights (batched, emit fp16) ----------------
struct WCfg {
    const float* Wl; const float* Wr; const float* b;
    __half* w; float* bc;
    int Din, nm, selfid, m0, m1, m2;
};
struct WAll { WCfg c[6]; };

__global__ void build_wcat_all(WAll wa) {
    WCfg cf = wa.c[blockIdx.y];
    int K = (cf.nm + 1) * cf.Din;
    int idx = blockIdx.x * blockDim.x + threadIdx.x;
    if (idx >= 64 * K) return;
    int d = idx / K, c = idx % K;
    int seg = c / cf.Din, k = c % cf.Din;
    int ms[3] = {cf.m0, cf.m1, cf.m2};
    int stride = 64 * cf.Din;
    float v;
    if (seg < cf.nm) {
        v = cf.Wl[ms[seg] * stride + d * cf.Din + k];
    } else {
        v = cf.Wl[cf.selfid * stride + d * cf.Din + k] + cf.Wr[cf.selfid * stride + d * cf.Din + k];
        for (int i = 0; i < cf.nm; i++) v += cf.Wr[ms[i] * stride + d * cf.Din + k];
    }
    cf.w[d * K + c] = __float2half_rn(v);
    if (c == 0) {
        float bb = cf.b[cf.selfid * 64 + d];
        for (int i = 0; i < cf.nm; i++) bb += cf.b[ms[i] * 64 + d];
        cf.bc[d] = bb;
    }
}

// ---------------- fused gather + fp16 tensor GEMM ----------------
__device__ __forceinline__ void mma_f16(float& d0, float& d1, float& d2, float& d3,
                                        uint32_t a0, uint32_t a1, uint32_t a2, uint32_t a3,
                                        uint32_t b0, uint32_t b1) {
    asm volatile("mma.sync.aligned.m16n8k16.row.col.f32.f16.f16.f32 "
                 "{%0,%1,%2,%3}, {%4,%5,%6,%7}, {%8,%9}, {%0,%1,%2,%3};"
                 : "+f"(d0), "+f"(d1), "+f"(d2), "+f"(d3)
                 : "r"(a0), "r"(a1), "r"(a2), "r"(a3), "r"(b0), "r"(b1));
}

__device__ __forceinline__ void acc_h4(float4& a, uint2 rw) {
    __half2 h0 = *reinterpret_cast<__half2*>(&rw.x);
    __half2 h1 = *reinterpret_cast<__half2*>(&rw.y);
    float2 f0 = __half22float2(h0);
    float2 f1 = __half22float2(h1);
    a.x += f0.x; a.y += f0.y; a.z += f1.x; a.w += f1.y;
}

struct TypeParams {
    const int* rp[3];
    const int* ci[3];
    const void* src[3];
    const void* xself;
    const __half* wcat;
    const float* bcat;
    float* out;
    int N;
    int nseg;
    int K;
    int mode;
    int blk0;
};
struct LayerParams {
    TypeParams t[3];
    const float* linW; const float* linb; const float* pa;
};

template <int DIN, bool SRCF16>
__global__ void __launch_bounds__(512, 3) fused_multi(LayerParams lp) {
    constexpr int S2 = DIN + 8;           // smem row stride in halves
    constexpr int G = DIN / 4;            // 4 elements per lane
    constexpr int NPI = 512 / G;
    constexpr int NIT = 128 / NPI;
    constexpr int C8 = DIN / 8;           // uint4 (8 halves) per weight-row chunk

    __shared__ __half sA[128 * S2];
    __shared__ __half sB[64 * S2];
    __shared__ float sred[512];

    int bx = blockIdx.x;
    int ty = (bx >= lp.t[2].blk0) ? 2 : (bx >= lp.t[1].blk0) ? 1 : 0;
    const TypeParams& tp = lp.t[ty];
    int nbase = (bx - tp.blk0) * 128;
    int N = tp.N;
    int nseg = tp.nseg;
    int K = tp.K;

    int tid = threadIdx.x;
    int warp = tid >> 5, lane = tid & 31;
    int wm = warp >> 2, wn = warp & 3;
    int r = lane >> 2, c = lane & 3;

    float acc[2][2][4];
#pragma unroll
    for (int mi = 0; mi < 2; mi++)
#pragma unroll
        for (int ni = 0; ni < 2; ni++) {
            int col = wn * 16 + ni * 8 + 2 * c;
            acc[mi][ni][0] = acc[mi][ni][2] = tp.bcat[col];
            acc[mi][ni][1] = acc[mi][ni][3] = tp.bcat[col + 1];
        }

    int g = tid & (G - 1);
    int nl0 = tid / G;

    for (int seg = 0; seg <= nseg; seg++) {
        bool isself = (seg == nseg);
        const int* rp = tp.rp[isself ? 0 : seg];
        const int* ci = tp.ci[isself ? 0 : seg];
        const void* src = tp.src[isself ? 0 : seg];

        // ---- stage fp16 weight slice [64][DIN] ----
        if (tid < 64 * C8) {
            int row = tid / C8, cc = tid % C8;
            uint4 w = *reinterpret_cast<const uint4*>(tp.wcat + (size_t)row * K + seg * DIN + cc * 8);
            *reinterpret_cast<uint4*>(&sB[(size_t)row * S2 + cc * 8]) = w;
        }

        // ---- gather / copy A slice [128][DIN] into fp16 smem ----
#pragma unroll
        for (int it = 0; it < NIT; it++) {
            int nl = it * NPI + nl0;
            int node = nbase + nl;
            bool valid = node < N;
            __half* ar = &sA[(size_t)nl * S2 + g * 4];
            uint2 stv;
            if (!isself) {
                int beg = 0, end = 0;
                if (valid) { beg = rp[node]; end = rp[node + 1]; }
                float4 a4 = make_float4(0.f, 0.f, 0.f, 0.f);
                if (SRCF16) {
                    const __half* sp = (const __half*)src + g * 4;
                    int e = beg;
                    for (; e + 4 <= end; e += 4) {
                        int i0 = ci[e], i1 = ci[e + 1], i2 = ci[e + 2], i3 = ci[e + 3];
                        uint2 v0 = *reinterpret_cast<const uint2*>(sp + (size_t)i0 * DIN);
                        uint2 v1 = *reinterpret_cast<const uint2*>(sp + (size_t)i1 * DIN);
                        uint2 v2 = *reinterpret_cast<const uint2*>(sp + (size_t)i2 * DIN);
                        uint2 v3 = *reinterpret_cast<const uint2*>(sp + (size_t)i3 * DIN);
                        acc_h4(a4, v0); acc_h4(a4, v1); acc_h4(a4, v2); acc_h4(a4, v3);
                    }
                    for (; e < end; e++) {
                        uint2 v0 = *reinterpret_cast<const uint2*>(sp + (size_t)ci[e] * DIN);
                        acc_h4(a4, v0);
                    }
                } else {
                    const float* sp = (const float*)src + g * 4;
                    int e = beg;
                    for (; e + 4 <= end; e += 4) {
                        int i0 = ci[e], i1 = ci[e + 1], i2 = ci[e + 2], i3 = ci[e + 3];
                        float4 v0 = *reinterpret_cast<const float4*>(sp + (size_t)i0 * DIN);
                        float4 v1 = *reinterpret_cast<const float4*>(sp + (size_t)i1 * DIN);
                        float4 v2 = *reinterpret_cast<const float4*>(sp + (size_t)i2 * DIN);
                        float4 v3 = *reinterpret_cast<const float4*>(sp + (size_t)i3 * DIN);
                        a4.x += (v0.x + v1.x) + (v2.x + v3.x);
                        a4.y += (v0.y + v1.y) + (v2.y + v3.y);
                        a4.z += (v0.z + v1.z) + (v2.z + v3.z);
                        a4.w += (v0.w + v1.w) + (v2.w + v3.w);
                    }
                    for (; e < end; e++) {
                        float4 v0 = *reinterpret_cast<const float4*>(sp + (size_t)ci[e] * DIN);
                        a4.x += v0.x; a4.y += v0.y; a4.z += v0.z; a4.w += v0.w;
                    }
                }
                float inv = (end > beg) ? 1.0f / (float)(end - beg) : 0.0f;
                __half2 h01 = __floats2half2_rn(a4.x * inv, a4.y * inv);
                __half2 h23 = __floats2half2_rn(a4.z * inv, a4.w * inv);
                stv.x = *reinterpret_cast<uint32_t*>(&h01);
                stv.y = *reinterpret_cast<uint32_t*>(&h23);
            } else {
                if (SRCF16) {
                    stv = make_uint2(0u, 0u);
                    if (valid) stv = *reinterpret_cast<const uint2*>((const __half*)tp.xself + (size_t)node * DIN + g * 4);
                } else {
                    float4 xs = make_float4(0.f, 0.f, 0.f, 0.f);
                    if (valid) xs = *reinterpret_cast<const float4*>((const float*)tp.xself + (size_t)node * DIN + g * 4);
                    __half2 h01 = __floats2half2_rn(xs.x, xs.y);
                    __half2 h23 = __floats2half2_rn(xs.z, xs.w);
                    stv.x = *reinterpret_cast<uint32_t*>(&h01);
                    stv.y = *reinterpret_cast<uint32_t*>(&h23);
                }
            }
            *reinterpret_cast<uint2*>(ar) = stv;
        }
        __syncthreads();

        // ---- f16 mma over this K-chunk (k16 steps) ----
#pragma unroll
        for (int k0 = 0; k0 < DIN; k0 += 16) {
            uint32_t bf0[2], bf1[2];
#pragma unroll
            for (int ni = 0; ni < 2; ni++) {
                const __half* pb = &sB[(size_t)(wn * 16 + ni * 8 + r) * S2 + k0 + 2 * c];
                bf0[ni] = *reinterpret_cast<const uint32_t*>(pb);
                bf1[ni] = *reinterpret_cast<const uint32_t*>(pb + 8);
            }
#pragma unroll
            for (int mi = 0; mi < 2; mi++) {
                const __half* pa = &sA[(size_t)(wm * 32 + mi * 16 + r) * S2 + k0 + 2 * c];
                uint32_t a0 = *reinterpret_cast<const uint32_t*>(pa);
                uint32_t a1 = *reinterpret_cast<const uint32_t*>(pa + 8 * S2);
                uint32_t a2 = *reinterpret_cast<const uint32_t*>(pa + 8);
                uint32_t a3 = *reinterpret_cast<const uint32_t*>(pa + 8 * S2 + 8);
#pragma unroll
                for (int ni = 0; ni < 2; ni++)
                    mma_f16(acc[mi][ni][0], acc[mi][ni][1], acc[mi][ni][2], acc[mi][ni][3],
                            a0, a1, a2, a3, bf0[ni], bf1[ni]);
            }
        }
        __syncthreads();
    }

    // ---- epilogue ----
    if (tp.mode == 0) {
        if (!SRCF16) {
            __half* o16 = reinterpret_cast<__half*>(tp.out);
#pragma unroll
            for (int mi = 0; mi < 2; mi++) {
                int m0 = nbase + wm * 32 + mi * 16 + r;
#pragma unroll
                for (int ni = 0; ni < 2; ni++) {
                    int col = wn * 16 + ni * 8 + 2 * c;
                    if (m0 < N) {
                        __half2 v = __floats2half2_rn(fmaxf(acc[mi][ni][0], 0.f), fmaxf(acc[mi][ni][1], 0.f));
                        *reinterpret_cast<uint32_t*>(o16 + (size_t)m0 * 64 + col) = *reinterpret_cast<uint32_t*>(&v);
                    }
                    if (m0 + 8 < N) {
                        __half2 v = __floats2half2_rn(fmaxf(acc[mi][ni][2], 0.f), fmaxf(acc[mi][ni][3], 0.f));
                        *reinterpret_cast<uint32_t*>(o16 + (size_t)(m0 + 8) * 64 + col) = *reinterpret_cast<uint32_t*>(&v);
                    }
                }
            }
        } else {
            float* outp = tp.out;
#pragma unroll
            for (int mi = 0; mi < 2; mi++) {
                int m0 = nbase + wm * 32 + mi * 16 + r;
#pragma unroll
                for (int ni = 0; ni < 2; ni++) {
                    int col = wn * 16 + ni * 8 + 2 * c;
                    if (m0 < N) {
                        float2 v = make_float2(fmaxf(acc[mi][ni][0], 0.f), fmaxf(acc[mi][ni][1], 0.f));
                        *reinterpret_cast<float2*>(outp + (size_t)m0 * 64 + col) = v;
                    }
                    if (m0 + 8 < N) {
                        float2 v = make_float2(fmaxf(acc[mi][ni][2], 0.f), fmaxf(acc[mi][ni][3], 0.f));
                        *reinterpret_cast<float2*>(outp + (size_t)(m0 + 8) * 64 + col) = v;
                    }
                }
            }
        }
    } else {
        float lb = lp.linb[0];
        float ap = lp.pa[0];
        float pl[2] = {0.f, 0.f}, ph[2] = {0.f, 0.f};
#pragma unroll
        for (int mi = 0; mi < 2; mi++) {
#pragma unroll
            for (int ni = 0; ni < 2; ni++) {
                int col = wn * 16 + ni * 8 + 2 * c;
                float w0 = lp.linW[col], w1 = lp.linW[col + 1];
                pl[mi] += fmaxf(acc[mi][ni][0], 0.f) * w0 + fmaxf(acc[mi][ni][1], 0.f) * w1;
                ph[mi] += fmaxf(acc[mi][ni][2], 0.f) * w0 + fmaxf(acc[mi][ni][3], 0.f) * w1;
            }
            pl[mi] += __shfl_xor_sync(0xffffffffu, pl[mi], 1);
            pl[mi] += __shfl_xor_sync(0xffffffffu, pl[mi], 2);
            ph[mi] += __shfl_xor_sync(0xffffffffu, ph[mi], 1);
            ph[mi] += __shfl_xor_sync(0xffffffffu, ph[mi], 2);
        }
        if (c == 0) {
#pragma unroll
            for (int mi = 0; mi < 2; mi++) {
                sred[wn * 128 + wm * 32 + mi * 16 + r] = pl[mi];
                sred[wn * 128 + wm * 32 + mi * 16 + r + 8] = ph[mi];
            }
        }
        __syncthreads();
        if (tid < 128) {
            float v = sred[tid] + sred[128 + tid] + sred[256 + tid] + sred[384 + tid] + lb;
            int n = nbase + tid;
            if (n < N) tp.out[n] = (v >= 0.f) ? v : ap * v;
        }
    }
}

// ---------------- launch ----------------
extern "C" void kernel_launch(void* const* d_in, const int* in_sizes, int n_in,
                              void* d_out, int out_size) {
    const float* x_pf = (const float*)d_in[0];
    const float* x_gw = (const float*)d_in[1];
    const float* x_sw = (const float*)d_in[2];
    const float* W1l  = (const float*)d_in[3];
    const float* b1l  = (const float*)d_in[4];
    const float* W1r  = (const float*)d_in[5];
    const float* W2l  = (const float*)d_in[6];
    const float* b2l  = (const float*)d_in[7];
    const float* W2r  = (const float*)d_in[8];
    const float* linW = (const float*)d_in[9];
    const float* linb = (const float*)d_in[10];
    const float* pa   = (const float*)d_in[11];
    const int* eis[7] = {
        (const int*)d_in[12],  // pf_gw
        (const int*)d_in[16],  // sw_gw
        (const int*)d_in[18],  // gw_gw
        (const int*)d_in[13],  // gw_pf
        (const int*)d_in[15],  // sw_pf
        (const int*)d_in[14],  // pf_sw
        (const int*)d_in[17],  // gw_sw
    };
    float* out = (float*)d_out;
    int E = in_sizes[12] / 2;

    float* scr;
    cudaGetSymbolAddress((void**)&scr, g_scratch);

    __half* h1_pf = reinterpret_cast<__half*>(scr + OFF_H1);
    __half* h1_gw = h1_pf + (size_t)NPF * 64;
    __half* h1_sw = h1_gw + (size_t)NGW * 64;

    int* cnt_base    = (int*)(scr + OFF_CNT);
    int* fill_base   = (int*)(scr + OFF_FILL);
    int* incl        = (int*)(scr + OFF_INCL);
    int* bsums       = (int*)(scr + OFF_BSUMS);
    int* rowptr_base = (int*)(scr + OFF_ROWPTR);
    int* colidx_base = (int*)(scr + OFF_COLIDX);

    const int ns[7] = {NGW, NGW, NGW, NPF, NPF, NSW, NSW};
    ScanCfg sc;
    int cnt_pad_total = 0;
    {
        int po = 0, ro = 0;
        for (int t = 0; t < 7; t++) {
            sc.ps[t] = po;
            sc.n[t] = ns[t];
            sc.nblk[t] = (ns[t] + 1023) / 1024;
            sc.rpo[t] = ro;
            po += sc.nblk[t] * 1024;
            ro += ns[t] + 1;
        }
        cnt_pad_total = po;
    }

    Ptrs7i pei, prp;
    Ptrs7o pcnt, pfill, pcol;
    int* rps[7]; int* cols[7];
    for (int t = 0; t < 7; t++) {
        pei.p[t]  = eis[t];
        pcnt.p[t] = cnt_base + sc.ps[t];
        pfill.p[t] = fill_base + sc.ps[t];
        rps[t] = rowptr_base + sc.rpo[t];
        prp.p[t] = rps[t];
        cols[t] = colidx_base + (size_t)t * EMAX;
        pcol.p[t] = cols[t];
    }

    // weight regions: float-sized slots, used as halves (2x slack). bcat fp32.
    float* wbase  = scr + OFF_WCAT;
    __half* wL1_gw = (__half*)(wbase);
    __half* wL1_pf = (__half*)(wbase + 8192);
    __half* wL1_sw = (__half*)(wbase + 14336);
    __half* wL2_gw = (__half*)(wbase + 20480);
    __half* wL2_pf = (__half*)(wbase + 36864);
    __half* wL2_sw = (__half*)(wbase + 49152);
    float* bL1_gw = wbase + 61440;
    float* bL1_pf = bL1_gw + 64;
    float* bL1_sw = bL1_pf + 64;
    float* bL2_gw = bL1_sw + 64;
    float* bL2_pf = bL2_gw + 64;
    float* bL2_sw = bL2_pf + 64;

    // ---- CSR build ----
    cudaMemsetAsync(cnt_base, 0, (size_t)cnt_pad_total * sizeof(int), 0);
    cudaMemsetAsync(fill_base, 0, (size_t)cnt_pad_total * sizeof(int), 0);
    {
        dim3 g((E + 255) / 256, 7);
        count_all<<<g, 256>>>(pei, pcnt, E);
    }
    {
        dim3 g(300, 7);
        scan_partial<<<g, 1024>>>(cnt_base, incl, bsums, sc);
        dim3 g2(1, 7);
        scan_bsums<<<g2, 512>>>(bsums, sc);
        dim3 g3((NGW + 255) / 256, 7);
        scan_final<<<g3, 256>>>(incl, bsums, rowptr_base, sc);
    }
    {
        dim3 g((E + 255) / 256, 7);
        scatter_all<<<g, 256>>>(pei, prp, pfill, pcol, E);
    }

    // ---- weights (fp16) ----
    {
        WAll wa;
        wa.c[0] = {W1l, W1r, b1l, wL1_gw, bL1_gw, 32, 3, 7, 0, 4, 6};
        wa.c[1] = {W1l, W1r, b1l, wL1_pf, bL1_pf, 32, 2, 9, 1, 3, -1};
        wa.c[2] = {W1l, W1r, b1l, wL1_sw, bL1_sw, 32, 2, 8, 2, 5, -1};
        wa.c[3] = {W2l, W2r, b2l, wL2_gw, bL2_gw, 64, 3, 7, 0, 4, 6};
        wa.c[4] = {W2l, W2r, b2l, wL2_pf, bL2_pf, 64, 2, 9, 1, 3, -1};
        wa.c[5] = {W2l, W2r, b2l, wL2_sw, bL2_sw, 64, 2, 8, 2, 5, -1};
        dim3 g(64, 6);
        build_wcat_all<<<g, 256>>>(wa);
    }

    const int BGW = (NGW + 127) / 128;   // 2344
    const int BPF = (NPF + 127) / 128;   // 469
    const int BSW = (NSW + 127) / 128;   // 469
    const int BTOT = BGW + BPF + BSW;    // 3282

    // ---- layer 1 (Din=32, fp32 x -> fp16 h1) ----
    {
        LayerParams lp;
        lp.linW = linW; lp.linb = linb; lp.pa = pa;
        lp.t[0] = {{rps[0], rps[1], rps[2]}, {cols[0], cols[1], cols[2]},
                   {x_pf, x_sw, x_gw}, x_gw, wL1_gw, bL1_gw, (float*)h1_gw,
                   NGW, 3, 128, 0, 0};
        lp.t[1] = {{rps[3], rps[4], rps[4]}, {cols[3], cols[4], cols[4]},
                   {x_gw, x_sw, x_sw}, x_pf, wL1_pf, bL1_pf, (float*)h1_pf,
                   NPF, 2, 96, 0, BGW};
        lp.t[2] = {{rps[5], rps[6], rps[6]}, {cols[5], cols[6], cols[6]},
                   {x_pf, x_gw, x_gw}, x_sw, wL1_sw, bL1_sw, (float*)h1_sw,
                   NSW, 2, 96, 0, BGW + BPF};
        fused_multi<32, false><<<BTOT, 512>>>(lp);
    }

    // ---- layer 2 (Din=64, fp16 h1 sources) ----
    // out layout: out_gw [NGW], out_sw [NSW], h_pf [NPF*64]
    {
        LayerParams lp;
        lp.linW = linW; lp.linb = linb; lp.pa = pa;
        lp.t[0] = {{rps[0], rps[1], rps[2]}, {cols[0], cols[1], cols[2]},
                   {h1_pf, h1_sw, h1_gw}, h1_gw, wL2_gw, bL2_gw, out,
                   NGW, 3, 256, 1, 0};
        lp.t[1] = {{rps[3], rps[4], rps[4]}, {cols[3], cols[4], cols[4]},
                   {h1_gw, h1_sw, h1_sw}, h1_pf, wL2_pf, bL2_pf, out + NGW + NSW,
                   NPF, 2, 192, 0, BGW};
        lp.t[2] = {{rps[5], rps[6], rps[6]}, {cols[5], cols[6], cols[6]},
                   {h1_pf, h1_gw, h1_gw}, h1_sw, wL2_sw, bL2_sw, out + NGW,
                   NSW, 2, 192, 1, BGW + BPF};
        fused_multi<64, true><<<BTOT, 512>>>(lp);
    }
}

// round 16
// speedup vs baseline: 1.5479x; 1.0581x over previous
#include <cuda_runtime.h>
#include <cuda_fp16.h>
#include <cstddef>
#include <cstdint>

#define NPF 60000
#define NGW 300000
#define NSW 60000
#define EMAX 1000000

// ---------------- scratch layout (4-byte units, ALL multiples of 4) ----------------
static const size_t OFF_H1     = 0;           // h1 as fp16 halves
static const size_t OFF_CNT    = 26880000;
static const size_t OFF_INCL   = 29206528;
static const size_t OFF_BSUMS  = 30369792;    // 7*512
static const size_t OFF_COLIDX = 31513384;    // 7,000,000
static const size_t OFF_WCAT   = 38513384;    // float-sized slots, used as halves

__device__ float g_scratch[38600000];   // ~155 MB

// types: 0 pf_gw, 1 sw_gw, 2 gw_gw, 3 gw_pf, 4 sw_pf, 5 pf_sw, 6 gw_sw
struct ScanCfg { int ps[7]; int nblk[7]; int n[7]; };
struct Ptrs7i { const int* p[7]; };
struct Ptrs7o { int* p[7]; };

// ---------------- CSR build (batched, rowptr-free) ----------------
__global__ void count_all(Ptrs7i ei, Ptrs7o cnt, int E) {
    int t = blockIdx.y;
    int i = blockIdx.x * blockDim.x + threadIdx.x;
    if (i < E) atomicAdd(&cnt.p[t][ei.p[t][E + i]], 1);
}

// warp-shuffle block scan (2 barriers)
__global__ void scan_partial(const int* __restrict__ cnt, int* __restrict__ incl,
                             int* __restrict__ bsums, ScanCfg sc) {
    int t = blockIdx.y;
    if ((int)blockIdx.x >= sc.nblk[t]) return;
    __shared__ int wsum[32];
    int tid = threadIdx.x;
    int lane = tid & 31, w = tid >> 5;
    int base = sc.ps[t] + blockIdx.x * 1024;
    int x = cnt[base + tid];
#pragma unroll
    for (int off = 1; off < 32; off <<= 1) {
        int y = __shfl_up_sync(0xffffffffu, x, off);
        if (lane >= off) x += y;
    }
    if (lane == 31) wsum[w] = x;
    __syncthreads();
    if (w == 0) {
        int s = wsum[lane];
#pragma unroll
        for (int off = 1; off < 32; off <<= 1) {
            int y = __shfl_up_sync(0xffffffffu, s, off);
            if (lane >= off) s += y;
        }
        wsum[lane] = s;
    }
    __syncthreads();
    int add = (w > 0) ? wsum[w - 1] : 0;
    int inc = x + add;
    incl[base + tid] = inc;
    if (tid == 1023) bsums[t * 512 + blockIdx.x] = inc;
}

__global__ void scan_bsums(int* __restrict__ bs, ScanCfg sc) {
    int t = blockIdx.y;
    int nb = sc.nblk[t];
    __shared__ int s[512];
    int tid = threadIdx.x;
    int v = (tid < nb) ? bs[t * 512 + tid] : 0;
    s[tid] = v; __syncthreads();
#pragma unroll
    for (int off = 1; off < 512; off <<= 1) {
        int t2 = (tid >= off) ? s[tid - off] : 0;
        __syncthreads();
        s[tid] += t2;
        __syncthreads();
    }
    if (tid < nb) bs[t * 512 + tid] = s[tid] - v;   // exclusive
}

// slot edges using cnt as a countdown cursor: end = incl[d]+bs; slot = end - atomicSub(cnt[d],1)
__global__ void scatter_all(Ptrs7i ei, Ptrs7i incl, Ptrs7o cnt, const int* __restrict__ bs,
                            Ptrs7o col, int E) {
    int t = blockIdx.y;
    int i = blockIdx.x * blockDim.x + threadIdx.x;
    if (i < E) {
        int s = ei.p[t][i];
        int d = ei.p[t][E + i];
        int end = incl.p[t][d] + bs[t * 512 + (d >> 10)];
        int c = atomicSub(&cnt.p[t][d], 1);
        col.p[t][end - c] = s;
    }
}

// ---------------- combined weights (batched, emit fp16) ----------------
struct WCfg {
    const float* Wl; const float* Wr; const float* b;
    __half* w; float* bc;
    int Din, nm, selfid, m0, m1, m2;
};
struct WAll { WCfg c[6]; };

__global__ void build_wcat_all(WAll wa) {
    WCfg cf = wa.c[blockIdx.y];
    int K = (cf.nm + 1) * cf.Din;
    int idx = blockIdx.x * blockDim.x + threadIdx.x;
    if (idx >= 64 * K) return;
    int d = idx / K, c = idx % K;
    int seg = c / cf.Din, k = c % cf.Din;
    int ms[3] = {cf.m0, cf.m1, cf.m2};
    int stride = 64 * cf.Din;
    float v;
    if (seg < cf.nm) {
        v = cf.Wl[ms[seg] * stride + d * cf.Din + k];
    } else {
        v = cf.Wl[cf.selfid * stride + d * cf.Din + k] + cf.Wr[cf.selfid * stride + d * cf.Din + k];
        for (int i = 0; i < cf.nm; i++) v += cf.Wr[ms[i] * stride + d * cf.Din + k];
    }
    cf.w[d * K + c] = __float2half_rn(v);
    if (c == 0) {
        float bb = cf.b[cf.selfid * 64 + d];
        for (int i = 0; i < cf.nm; i++) bb += cf.b[ms[i] * 64 + d];
        cf.bc[d] = bb;
    }
}

// ---------------- fused gather + fp16 tensor GEMM ----------------
__device__ __forceinline__ void mma_f16(float& d0, float& d1, float& d2, float& d3,
                                        uint32_t a0, uint32_t a1, uint32_t a2, uint32_t a3,
                                        uint32_t b0, uint32_t b1) {
    asm volatile("mma.sync.aligned.m16n8k16.row.col.f32.f16.f16.f32 "
                 "{%0,%1,%2,%3}, {%4,%5,%6,%7}, {%8,%9}, {%0,%1,%2,%3};"
                 : "+f"(d0), "+f"(d1), "+f"(d2), "+f"(d3)
                 : "r"(a0), "r"(a1), "r"(a2), "r"(a3), "r"(b0), "r"(b1));
}

__device__ __forceinline__ void acc_h4(float4& a, uint2 rw) {
    __half2 h0 = *reinterpret_cast<__half2*>(&rw.x);
    __half2 h1 = *reinterpret_cast<__half2*>(&rw.y);
    float2 f0 = __half22float2(h0);
    float2 f1 = __half22float2(h1);
    a.x += f0.x; a.y += f0.y; a.z += f1.x; a.w += f1.y;
}

struct TypeParams {
    const int* il[3];      // inclusive per-1024-block scans
    const int* bsp[3];     // per-type exclusive block sums (512 ints)
    const int* ci[3];
    const void* src[3];
    const void* xself;
    const __half* wcat;
    const float* bcat;
    float* out;
    int N;
    int nseg;
    int K;
    int mode;
    int blk0;
};
struct LayerParams {
    TypeParams t[3];
    const float* linW; const float* linb; const float* pa;
};

template <int DIN, bool SRCF16>
__global__ void __launch_bounds__(512, 3) fused_multi(LayerParams lp) {
    constexpr int S2 = DIN + 8;           // smem row stride in halves
    constexpr int G = DIN / 4;            // 4 elements per lane
    constexpr int NPI = 512 / G;
    constexpr int NIT = 128 / NPI;
    constexpr int C8 = DIN / 8;           // uint4 (8 halves) per weight-row chunk

    __shared__ __half sA[128 * S2];
    __shared__ __half sB[64 * S2];
    __shared__ float sred[512];

    int bx = blockIdx.x;
    int ty = (bx >= lp.t[2].blk0) ? 2 : (bx >= lp.t[1].blk0) ? 1 : 0;
    const TypeParams& tp = lp.t[ty];
    int nbase = (bx - tp.blk0) * 128;
    int N = tp.N;
    int nseg = tp.nseg;
    int K = tp.K;

    int tid = threadIdx.x;
    int warp = tid >> 5, lane = tid & 31;
    int wm = warp >> 2, wn = warp & 3;
    int r = lane >> 2, c = lane & 3;

    float acc[2][2][4];
#pragma unroll
    for (int mi = 0; mi < 2; mi++)
#pragma unroll
        for (int ni = 0; ni < 2; ni++) {
            int col = wn * 16 + ni * 8 + 2 * c;
            acc[mi][ni][0] = acc[mi][ni][2] = tp.bcat[col];
            acc[mi][ni][1] = acc[mi][ni][3] = tp.bcat[col + 1];
        }

    int g = tid & (G - 1);
    int nl0 = tid / G;

    for (int seg = 0; seg <= nseg; seg++) {
        bool isself = (seg == nseg);
        const int* il = tp.il[isself ? 0 : seg];
        const int* bsp = tp.bsp[isself ? 0 : seg];
        const int* ci = tp.ci[isself ? 0 : seg];
        const void* src = tp.src[isself ? 0 : seg];

        // ---- stage fp16 weight slice [64][DIN] ----
        if (tid < 64 * C8) {
            int row = tid / C8, cc = tid % C8;
            uint4 w = *reinterpret_cast<const uint4*>(tp.wcat + (size_t)row * K + seg * DIN + cc * 8);
            *reinterpret_cast<uint4*>(&sB[(size_t)row * S2 + cc * 8]) = w;
        }

        // ---- gather / copy A slice [128][DIN] into fp16 smem ----
#pragma unroll
        for (int it = 0; it < NIT; it++) {
            int nl = it * NPI + nl0;
            int node = nbase + nl;
            bool valid = node < N;
            __half* ar = &sA[(size_t)nl * S2 + g * 4];
            uint2 stv;
            if (!isself) {
                int beg = 0, end = 0;
                if (valid) {
                    end = il[node] + bsp[node >> 10];
                    beg = (node > 0) ? (il[node - 1] + bsp[(node - 1) >> 10]) : 0;
                }
                float4 a4 = make_float4(0.f, 0.f, 0.f, 0.f);
                if (SRCF16) {
                    const __half* sp = (const __half*)src + g * 4;
                    int e = beg;
                    for (; e + 4 <= end; e += 4) {
                        int i0 = ci[e], i1 = ci[e + 1], i2 = ci[e + 2], i3 = ci[e + 3];
                        uint2 v0 = *reinterpret_cast<const uint2*>(sp + (size_t)i0 * DIN);
                        uint2 v1 = *reinterpret_cast<const uint2*>(sp + (size_t)i1 * DIN);
                        uint2 v2 = *reinterpret_cast<const uint2*>(sp + (size_t)i2 * DIN);
                        uint2 v3 = *reinterpret_cast<const uint2*>(sp + (size_t)i3 * DIN);
                        acc_h4(a4, v0); acc_h4(a4, v1); acc_h4(a4, v2); acc_h4(a4, v3);
                    }
                    for (; e < end; e++) {
                        uint2 v0 = *reinterpret_cast<const uint2*>(sp + (size_t)ci[e] * DIN);
                        acc_h4(a4, v0);
                    }
                } else {
                    const float* sp = (const float*)src + g * 4;
                    int e = beg;
                    for (; e + 4 <= end; e += 4) {
                        int i0 = ci[e], i1 = ci[e + 1], i2 = ci[e + 2], i3 = ci[e + 3];
                        float4 v0 = *reinterpret_cast<const float4*>(sp + (size_t)i0 * DIN);
                        float4 v1 = *reinterpret_cast<const float4*>(sp + (size_t)i1 * DIN);
                        float4 v2 = *reinterpret_cast<const float4*>(sp + (size_t)i2 * DIN);
                        float4 v3 = *reinterpret_cast<const float4*>(sp + (size_t)i3 * DIN);
                        a4.x += (v0.x + v1.x) + (v2.x + v3.x);
                        a4.y += (v0.y + v1.y) + (v2.y + v3.y);
                        a4.z += (v0.z + v1.z) + (v2.z + v3.z);
                        a4.w += (v0.w + v1.w) + (v2.w + v3.w);
                    }
                    for (; e < end; e++) {
                        float4 v0 = *reinterpret_cast<const float4*>(sp + (size_t)ci[e] * DIN);
                        a4.x += v0.x; a4.y += v0.y; a4.z += v0.z; a4.w += v0.w;
                    }
                }
                float inv = (end > beg) ? 1.0f / (float)(end - beg) : 0.0f;
                __half2 h01 = __floats2half2_rn(a4.x * inv, a4.y * inv);
                __half2 h23 = __floats2half2_rn(a4.z * inv, a4.w * inv);
                stv.x = *reinterpret_cast<uint32_t*>(&h01);
                stv.y = *reinterpret_cast<uint32_t*>(&h23);
            } else {
                if (SRCF16) {
                    stv = make_uint2(0u, 0u);
                    if (valid) stv = *reinterpret_cast<const uint2*>((const __half*)tp.xself + (size_t)node * DIN + g * 4);
                } else {
                    float4 xs = make_float4(0.f, 0.f, 0.f, 0.f);
                    if (valid) xs = *reinterpret_cast<const float4*>((const float*)tp.xself + (size_t)node * DIN + g * 4);
                    __half2 h01 = __floats2half2_rn(xs.x, xs.y);
                    __half2 h23 = __floats2half2_rn(xs.z, xs.w);
                    stv.x = *reinterpret_cast<uint32_t*>(&h01);
                    stv.y = *reinterpret_cast<uint32_t*>(&h23);
                }
            }
            *reinterpret_cast<uint2*>(ar) = stv;
        }
        __syncthreads();

        // ---- f16 mma over this K-chunk (k16 steps) ----
#pragma unroll
        for (int k0 = 0; k0 < DIN; k0 += 16) {
            uint32_t bf0[2], bf1[2];
#pragma unroll
            for (int ni = 0; ni < 2; ni++) {
                const __half* pb = &sB[(size_t)(wn * 16 + ni * 8 + r) * S2 + k0 + 2 * c];
                bf0[ni] = *reinterpret_cast<const uint32_t*>(pb);
                bf1[ni] = *reinterpret_cast<const uint32_t*>(pb + 8);
            }
#pragma unroll
            for (int mi = 0; mi < 2; mi++) {
                const __half* pa = &sA[(size_t)(wm * 32 + mi * 16 + r) * S2 + k0 + 2 * c];
                uint32_t a0 = *reinterpret_cast<const uint32_t*>(pa);
                uint32_t a1 = *reinterpret_cast<const uint32_t*>(pa + 8 * S2);
                uint32_t a2 = *reinterpret_cast<const uint32_t*>(pa + 8);
                uint32_t a3 = *reinterpret_cast<const uint32_t*>(pa + 8 * S2 + 8);
#pragma unroll
                for (int ni = 0; ni < 2; ni++)
                    mma_f16(acc[mi][ni][0], acc[mi][ni][1], acc[mi][ni][2], acc[mi][ni][3],
                            a0, a1, a2, a3, bf0[ni], bf1[ni]);
            }
        }
        __syncthreads();
    }

    // ---- epilogue ----
    if (tp.mode == 0) {
        if (!SRCF16) {
            __half* o16 = reinterpret_cast<__half*>(tp.out);
#pragma unroll
            for (int mi = 0; mi < 2; mi++) {
                int m0 = nbase + wm * 32 + mi * 16 + r;
#pragma unroll
                for (int ni = 0; ni < 2; ni++) {
                    int col = wn * 16 + ni * 8 + 2 * c;
                    if (m0 < N) {
                        __half2 v = __floats2half2_rn(fmaxf(acc[mi][ni][0], 0.f), fmaxf(acc[mi][ni][1], 0.f));
                        *reinterpret_cast<uint32_t*>(o16 + (size_t)m0 * 64 + col) = *reinterpret_cast<uint32_t*>(&v);
                    }
                    if (m0 + 8 < N) {
                        __half2 v = __floats2half2_rn(fmaxf(acc[mi][ni][2], 0.f), fmaxf(acc[mi][ni][3], 0.f));
                        *reinterpret_cast<uint32_t*>(o16 + (size_t)(m0 + 8) * 64 + col) = *reinterpret_cast<uint32_t*>(&v);
                    }
                }
            }
        } else {
            float* outp = tp.out;
#pragma unroll
            for (int mi = 0; mi < 2; mi++) {
                int m0 = nbase + wm * 32 + mi * 16 + r;
#pragma unroll
                for (int ni = 0; ni < 2; ni++) {
                    int col = wn * 16 + ni * 8 + 2 * c;
                    if (m0 < N) {
                        float2 v = make_float2(fmaxf(acc[mi][ni][0], 0.f), fmaxf(acc[mi][ni][1], 0.f));
                        *reinterpret_cast<float2*>(outp + (size_t)m0 * 64 + col) = v;
                    }
                    if (m0 + 8 < N) {
                        float2 v = make_float2(fmaxf(acc[mi][ni][2], 0.f), fmaxf(acc[mi][ni][3], 0.f));
                        *reinterpret_cast<float2*>(outp + (size_t)(m0 + 8) * 64 + col) = v;
                    }
                }
            }
        }
    } else {
        float lb = lp.linb[0];
        float ap = lp.pa[0];
        float pl[2] = {0.f, 0.f}, ph[2] = {0.f, 0.f};
#pragma unroll
        for (int mi = 0; mi < 2; mi++) {
#pragma unroll
            for (int ni = 0; ni < 2; ni++) {
                int col = wn * 16 + ni * 8 + 2 * c;
                float w0 = lp.linW[col], w1 = lp.linW[col + 1];
                pl[mi] += fmaxf(acc[mi][ni][0], 0.f) * w0 + fmaxf(acc[mi][ni][1], 0.f) * w1;
                ph[mi] += fmaxf(acc[mi][ni][2], 0.f) * w0 + fmaxf(acc[mi][ni][3], 0.f) * w1;
            }
            pl[mi] += __shfl_xor_sync(0xffffffffu, pl[mi], 1);
            pl[mi] += __shfl_xor_sync(0xffffffffu, pl[mi], 2);
            ph[mi] += __shfl_xor_sync(0xffffffffu, ph[mi], 1);
            ph[mi] += __shfl_xor_sync(0xffffffffu, ph[mi], 2);
        }
        if (c == 0) {
#pragma unroll
            for (int mi = 0; mi < 2; mi++) {
                sred[wn * 128 + wm * 32 + mi * 16 + r] = pl[mi];
                sred[wn * 128 + wm * 32 + mi * 16 + r + 8] = ph[mi];
            }
        }
        __syncthreads();
        if (tid < 128) {
            float v = sred[tid] + sred[128 + tid] + sred[256 + tid] + sred[384 + tid] + lb;
            int n = nbase + tid;
            if (n < N) tp.out[n] = (v >= 0.f) ? v : ap * v;
        }
    }
}

// ---------------- launch ----------------
extern "C" void kernel_launch(void* const* d_in, const int* in_sizes, int n_in,
                              void* d_out, int out_size) {
    const float* x_pf = (const float*)d_in[0];
    const float* x_gw = (const float*)d_in[1];
    const float* x_sw = (const float*)d_in[2];
    const float* W1l  = (const float*)d_in[3];
    const float* b1l  = (const float*)d_in[4];
    const float* W1r  = (const float*)d_in[5];
    const float* W2l  = (const float*)d_in[6];
    const float* b2l  = (const float*)d_in[7];
    const float* W2r  = (const float*)d_in[8];
    const float* linW = (const float*)d_in[9];
    const float* linb = (const float*)d_in[10];
    const float* pa   = (const float*)d_in[11];
    const int* eis[7] = {
        (const int*)d_in[12],  // pf_gw
        (const int*)d_in[16],  // sw_gw
        (const int*)d_in[18],  // gw_gw
        (const int*)d_in[13],  // gw_pf
        (const int*)d_in[15],  // sw_pf
        (const int*)d_in[14],  // pf_sw
        (const int*)d_in[17],  // gw_sw
    };
    float* out = (float*)d_out;
    int E = in_sizes[12] / 2;

    float* scr;
    cudaGetSymbolAddress((void**)&scr, g_scratch);

    __half* h1_pf = reinterpret_cast<__half*>(scr + OFF_H1);
    __half* h1_gw = h1_pf + (size_t)NPF * 64;
    __half* h1_sw = h1_gw + (size_t)NGW * 64;

    int* cnt_base    = (int*)(scr + OFF_CNT);
    int* incl        = (int*)(scr + OFF_INCL);
    int* bsums       = (int*)(scr + OFF_BSUMS);
    int* colidx_base = (int*)(scr + OFF_COLIDX);

    const int ns[7] = {NGW, NGW, NGW, NPF, NPF, NSW, NSW};
    ScanCfg sc;
    int cnt_pad_total = 0;
    {
        int po = 0;
        for (int t = 0; t < 7; t++) {
            sc.ps[t] = po;
            sc.n[t] = ns[t];
            sc.nblk[t] = (ns[t] + 1023) / 1024;
            po += sc.nblk[t] * 1024;
        }
        cnt_pad_total = po;
    }

    Ptrs7i pei, pincl;
    Ptrs7o pcnt, pcol;
    const int* ils[7]; int* cols[7];
    for (int t = 0; t < 7; t++) {
        pei.p[t]  = eis[t];
        pcnt.p[t] = cnt_base + sc.ps[t];
        ils[t] = incl + sc.ps[t];
        pincl.p[t] = ils[t];
        cols[t] = colidx_base + (size_t)t * EMAX;
        pcol.p[t] = cols[t];
    }
    const int* bsp7[7];
    for (int t = 0; t < 7; t++) bsp7[t] = bsums + t * 512;

    // weight regions: float-sized slots, used as halves (2x slack). bcat fp32.
    float* wbase  = scr + OFF_WCAT;
    __half* wL1_gw = (__half*)(wbase);
    __half* wL1_pf = (__half*)(wbase + 8192);
    __half* wL1_sw = (__half*)(wbase + 14336);
    __half* wL2_gw = (__half*)(wbase + 20480);
    __half* wL2_pf = (__half*)(wbase + 36864);
    __half* wL2_sw = (__half*)(wbase + 49152);
    float* bL1_gw = wbase + 61440;
    float* bL1_pf = bL1_gw + 64;
    float* bL1_sw = bL1_pf + 64;
    float* bL2_gw = bL1_sw + 64;
    float* bL2_pf = bL2_gw + 64;
    float* bL2_sw = bL2_pf + 64;

    // ---- CSR build (rowptr-free): memset + count + scan2 + scatter ----
    cudaMemsetAsync(cnt_base, 0, (size_t)cnt_pad_total * sizeof(int), 0);
    {
        dim3 g((E + 255) / 256, 7);
        count_all<<<g, 256>>>(pei, pcnt, E);
    }
    {
        dim3 g(300, 7);
        scan_partial<<<g, 1024>>>(cnt_base, incl, bsums, sc);
        dim3 g2(1, 7);
        scan_bsums<<<g2, 512>>>(bsums, sc);
    }
    {
        dim3 g((E + 255) / 256, 7);
        scatter_all<<<g, 256>>>(pei, pincl, pcnt, bsums, pcol, E);
    }

    // ---- weights (fp16) ----
    {
        WAll wa;
        wa.c[0] = {W1l, W1r, b1l, wL1_gw, bL1_gw, 32, 3, 7, 0, 4, 6};
        wa.c[1] = {W1l, W1r, b1l, wL1_pf, bL1_pf, 32, 2, 9, 1, 3, -1};
        wa.c[2] = {W1l, W1r, b1l, wL1_sw, bL1_sw, 32, 2, 8, 2, 5, -1};
        wa.c[3] = {W2l, W2r, b2l, wL2_gw, bL2_gw, 64, 3, 7, 0, 4, 6};
        wa.c[4] = {W2l, W2r, b2l, wL2_pf, bL2_pf, 64, 2, 9, 1, 3, -1};
        wa.c[5] = {W2l, W2r, b2l, wL2_sw, bL2_sw, 64, 2, 8, 2, 5, -1};
        dim3 g(64, 6);
        build_wcat_all<<<g, 256>>>(wa);
    }

    const int BGW = (NGW + 127) / 128;   // 2344
    const int BPF = (NPF + 127) / 128;   // 469
    const int BSW = (NSW + 127) / 128;   // 469
    const int BTOT = BGW + BPF + BSW;    // 3282

    // ---- layer 1 (Din=32, fp32 x -> fp16 h1) ----
    {
        LayerParams lp;
        lp.linW = linW; lp.linb = linb; lp.pa = pa;
        lp.t[0] = {{ils[0], ils[1], ils[2]}, {bsp7[0], bsp7[1], bsp7[2]},
                   {cols[0], cols[1], cols[2]},
                   {x_pf, x_sw, x_gw}, x_gw, wL1_gw, bL1_gw, (float*)h1_gw,
                   NGW, 3, 128, 0, 0};
        lp.t[1] = {{ils[3], ils[4], ils[4]}, {bsp7[3], bsp7[4], bsp7[4]},
                   {cols[3], cols[4], cols[4]},
                   {x_gw, x_sw, x_sw}, x_pf, wL1_pf, bL1_pf, (float*)h1_pf,
                   NPF, 2, 96, 0, BGW};
        lp.t[2] = {{ils[5], ils[6], ils[6]}, {bsp7[5], bsp7[6], bsp7[6]},
                   {cols[5], cols[6], cols[6]},
                   {x_pf, x_gw, x_gw}, x_sw, wL1_sw, bL1_sw, (float*)h1_sw,
                   NSW, 2, 96, 0, BGW + BPF};
        fused_multi<32, false><<<BTOT, 512>>>(lp);
    }

    // ---- layer 2 (Din=64, fp16 h1 sources) ----
    // out layout: out_gw [NGW], out_sw [NSW], h_pf [NPF*64]
    {
        LayerParams lp;
        lp.linW = linW; lp.linb = linb; lp.pa = pa;
        lp.t[0] = {{ils[0], ils[1], ils[2]}, {bsp7[0], bsp7[1], bsp7[2]},
                   {cols[0], cols[1], cols[2]},
                   {h1_pf, h1_sw, h1_gw}, h1_gw, wL2_gw, bL2_gw, out,
                   NGW, 3, 256, 1, 0};
        lp.t[1] = {{ils[3], ils[4], ils[4]}, {bsp7[3], bsp7[4], bsp7[4]},
                   {cols[3], cols[4], cols[4]},
                   {h1_gw, h1_sw, h1_sw}, h1_pf, wL2_pf, bL2_pf, out + NGW + NSW,
                   NPF, 2, 192, 0, BGW};
        lp.t[2] = {{ils[5], ils[6], ils[6]}, {bsp7[5], bsp7[6], bsp7[6]},
                   {cols[5], cols[6], cols[6]},
                   {h1_pf, h1_gw, h1_gw}, h1_sw, wL2_sw, bL2_sw, out + NGW,
                   NSW, 2, 192, 1, BGW + BPF};
        fused_multi<64, true><<<BTOT, 512>>>(lp);
    }
}